// round 3
// baseline (speedup 1.0000x reference)
#include <cuda_runtime.h>
#include <cuda_bf16.h>
#include <math.h>

// Problem constants (fixed by reference: x,y (4,2,32768) fp32, max_shift=128)
constexpr int T  = 32768;
constexpr int P  = 8;      // B*C pairs
constexpr int MS = 128;    // max_shift
constexpr int S  = 2 * MS + 1;  // 257 shifts

// Tiling: one wave of 128 blocks (16 chunks x 8 pairs), 520 threads each
constexpr int CHK    = 2048;
constexpr int NCHUNK = T / CHK;   // 16
constexpr int Z      = 8;         // time-slices per block
constexpr int G      = 65;        // shift groups of 4 -> covers shifts 0..259
constexpr int BD     = Z * G;     // 520 threads

// Scratch (atomic-free data, atomic completion counters)
__device__ float g_part[P][NCHUNK][264];   // [pair][chunk][shift]
__device__ float g_stats[P][NCHUNK][4];    // [pair][chunk][{Sy,Syy,Sx,Sxx}]
__device__ int   g_cnt[P];                 // zero-init; reset in-kernel for replay

__global__ __launch_bounds__(BD) void corr_fused(const float* __restrict__ x,
                                                 const float* __restrict__ y,
                                                 float* __restrict__ out) {
    __shared__ __align__(16) float smx[CHK + 264];  // x tile + halo (zero-padded OOB)
    __shared__ __align__(16) float smy[CHK];
    __shared__ float red[Z][G][4];
    __shared__ float wstats[8][4];
    __shared__ int   isLast;
    __shared__ float2 scH[MS], scT[MS];             // boundary prefix sums (x, x^2)
    __shared__ float tot[4];

    const int chunk = blockIdx.x;
    const int pair  = blockIdx.y;
    const float* xp = x + pair * T;
    const float* yp = y + pair * T;
    const int cbase = chunk * CHK;
    const int tid   = threadIdx.x;

    // ---- load tiles (x with halo; pad index = cbase - MS + i) ----
    for (int i = tid; i < CHK + 264; i += BD) {
        int gi = cbase - MS + i;
        smx[i] = (gi >= 0 && gi < T) ? xp[gi] : 0.0f;
    }
    for (int i = tid; i < CHK; i += BD) {
        smy[i] = yp[cbase + i];
    }
    __syncthreads();

    // ---- per-chunk statistics (first 8 warps) ----
    if (tid < 256) {
        float ly = 0.f, lyy = 0.f, lx = 0.f, lxx = 0.f;
        for (int i = tid; i < CHK; i += 256) {
            float yv = smy[i];      ly += yv; lyy += yv * yv;
            float xv = smx[MS + i]; lx += xv; lxx += xv * xv;
        }
        #pragma unroll
        for (int o = 16; o; o >>= 1) {
            ly  += __shfl_down_sync(0xffffffffu, ly,  o);
            lyy += __shfl_down_sync(0xffffffffu, lyy, o);
            lx  += __shfl_down_sync(0xffffffffu, lx,  o);
            lxx += __shfl_down_sync(0xffffffffu, lxx, o);
        }
        if ((tid & 31) == 0) {
            int w = tid >> 5;
            wstats[w][0] = ly; wstats[w][1] = lyy;
            wstats[w][2] = lx; wstats[w][3] = lxx;
        }
    }

    // ---- shifted dot products: sliding float4 register window ----
    const int g  = tid % G;          // shift group: shifts [4g, 4g+4)
    const int tz = tid / G;          // time slice
    const int t0 = tz * (CHK / Z);
    const int t1 = t0 + (CHK / Z);

    const float4* x4 = reinterpret_cast<const float4*>(smx);
    const float4* y4 = reinterpret_cast<const float4*>(smy);

    float a0 = 0.f, a1 = 0.f, a2 = 0.f, a3 = 0.f;
    int xi = (t0 + 4 * g) >> 2;
    float4 w0 = x4[xi];

    #pragma unroll 4
    for (int t = t0; t < t1; t += 4) {
        float4 w1 = x4[xi + 1];
        float4 yv = y4[t >> 2];
        a0 += yv.x * w0.x + yv.y * w0.y + yv.z * w0.z + yv.w * w0.w;
        a1 += yv.x * w0.y + yv.y * w0.z + yv.z * w0.w + yv.w * w1.x;
        a2 += yv.x * w0.z + yv.y * w0.w + yv.z * w1.x + yv.w * w1.y;
        a3 += yv.x * w0.w + yv.y * w1.x + yv.z * w1.y + yv.w * w1.z;
        w0 = w1;
        xi++;
    }

    red[tz][g][0] = a0; red[tz][g][1] = a1;
    red[tz][g][2] = a2; red[tz][g][3] = a3;
    __syncthreads();

    if (tid < G) {
        #pragma unroll
        for (int j = 0; j < 4; j++) {
            float s = 0.f;
            #pragma unroll
            for (int z = 0; z < Z; z++) s += red[z][tid][j];
            g_part[pair][chunk][4 * tid + j] = s;
        }
    }
    if (tid >= G && tid < G + 4) {
        int j = tid - G;
        float s = 0.f;
        #pragma unroll
        for (int w = 0; w < 8; w++) s += wstats[w][j];
        g_stats[pair][chunk][j] = s;
    }
    __syncthreads();

    // ---- completion handshake: last block of this pair finalizes ----
    if (tid == 0) {
        __threadfence();
        int old = atomicAdd(&g_cnt[pair], 1);
        isLast = (old == NCHUNK - 1) ? 1 : 0;
    }
    __syncthreads();
    if (!isLast) return;
    __threadfence();

    // =================== FINALIZE (one block per pair) ===================
    // Boundary arrays: head x[0..MS), tail reversed x[T-1-j]
    if (tid < MS) {
        float v = xp[tid];
        scH[tid] = make_float2(v, v * v);
    } else if (tid < 2 * MS) {
        int j = tid - MS;
        float v = xp[T - 1 - j];
        scT[j] = make_float2(v, v * v);
    } else if (tid < 2 * MS + 32) {
        // warp 8: gather per-chunk stats
        int lane = tid - 2 * MS;
        float4 v = (lane < NCHUNK) ? *reinterpret_cast<const float4*>(g_stats[pair][lane])
                                   : make_float4(0.f, 0.f, 0.f, 0.f);
        #pragma unroll
        for (int o = 8; o; o >>= 1) {
            v.x += __shfl_down_sync(0xffffffffu, v.x, o);
            v.y += __shfl_down_sync(0xffffffffu, v.y, o);
            v.z += __shfl_down_sync(0xffffffffu, v.z, o);
            v.w += __shfl_down_sync(0xffffffffu, v.w, o);
        }
        if (lane == 0) { tot[0] = v.x; tot[1] = v.y; tot[2] = v.z; tot[3] = v.w; }
    }
    __syncthreads();

    // Hillis-Steele inclusive scans over head and reversed tail (128 each)
    #pragma unroll
    for (int o = 1; o < MS; o <<= 1) {
        float2 v = make_float2(0.f, 0.f);
        const bool act = tid < 2 * MS;
        float2* arr = (tid < MS) ? scH : scT;
        const int j = (tid < MS) ? tid : tid - MS;
        if (act) {
            v = arr[j];
            if (j >= o) { v.x += arr[j - o].x; v.y += arr[j - o].y; }
        }
        __syncthreads();
        if (act) arr[j] = v;
        __syncthreads();
    }

    // ---- per-shift final Pearson value ----
    if (tid < S) {
        const float Sy  = tot[0], Syy = tot[1];
        const float Sx  = tot[2], Sxx = tot[3];
        const float invT = 1.0f / (float)T;
        const float my   = Sy * invT;
        const float vyy  = Syy - my * Sy;     // sum((y - my)^2)

        float part = 0.f;
        #pragma unroll
        for (int c = 0; c < NCHUNK; c++) part += g_part[pair][c][tid];

        const int d = tid - MS;
        float bx = 0.f, bxx = 0.f;
        if (d > 0)      { float2 h = scH[d - 1];  bx = h.x; bxx = h.y; }
        else if (d < 0) { float2 t2 = scT[-d - 1]; bx = t2.x; bxx = t2.y; }

        const float wsx  = Sx  - bx;
        const float wsxx = Sxx - bxx;
        const float num  = part - my * wsx;           // sum(xw * yc)
        const float vxx  = wsxx - wsx * wsx * invT;   // sum((xw - mean_xw)^2)
        out[tid * P + pair] = num * rsqrtf(vxx * vyy);
    }

    __syncthreads();
    if (tid == 0) g_cnt[pair] = 0;   // reset for next graph replay
}

extern "C" void kernel_launch(void* const* d_in, const int* in_sizes, int n_in,
                              void* d_out, int out_size) {
    const float* x = (const float*)d_in[0];
    const float* y = (const float*)d_in[1];
    float* out = (float*)d_out;

    corr_fused<<<dim3(NCHUNK, P), BD>>>(x, y, out);
}

// round 4
// speedup vs baseline: 1.0172x; 1.0172x over previous
#include <cuda_runtime.h>
#include <cuda_bf16.h>
#include <math.h>

// Problem constants (fixed by reference: x,y (4,2,32768) fp32, max_shift=128)
constexpr int T  = 32768;
constexpr int P  = 8;      // B*C pairs
constexpr int MS = 128;    // max_shift
constexpr int S  = 2 * MS + 1;  // 257 shifts

// Tiling: 256 blocks (32 chunks x 8 pairs), 528 threads, 2 CTAs/SM
constexpr int CHK    = 1024;
constexpr int NCHUNK = T / CHK;   // 32
constexpr int Z      = 16;        // time-slices per block
constexpr int G      = 33;        // shift groups of 8 -> covers shifts 0..263
constexpr int BD     = Z * G;     // 528 threads
constexpr int XH     = CHK + 272; // x tile + halo (needs up to CHK+266)

// Scratch (atomic-free data, atomic completion counters)
__device__ float g_part[P][NCHUNK][264];   // [pair][chunk][shift]
__device__ float g_stats[P][NCHUNK][4];    // [pair][chunk][{Sy,Syy,Sx,Sxx}]
__device__ int   g_cnt[P];                 // zero-init; reset in-kernel for replay

__global__ __launch_bounds__(BD) void corr_fused(const float* __restrict__ x,
                                                 const float* __restrict__ y,
                                                 float* __restrict__ out) {
    __shared__ __align__(16) float smx[XH];
    __shared__ __align__(16) float smy[CHK];
    __shared__ float red[Z][G][8];
    __shared__ float wstats[8][4];
    __shared__ int   isLast;
    __shared__ float2 scH[MS], scT[MS];    // boundary prefix sums (x, x^2)
    __shared__ float tot[4];

    const int chunk = blockIdx.x;
    const int pair  = blockIdx.y;
    const float* xp = x + pair * T;
    const float* yp = y + pair * T;
    const int cbase = chunk * CHK;
    const int tid   = threadIdx.x;

    // ---- load tiles (x with halo; pad index = cbase - MS + i) ----
    for (int i = tid; i < XH; i += BD) {
        int gi = cbase - MS + i;
        smx[i] = (gi >= 0 && gi < T) ? xp[gi] : 0.0f;
    }
    for (int i = tid; i < CHK; i += BD) {
        smy[i] = yp[cbase + i];
    }
    __syncthreads();

    // ---- per-chunk statistics (first 8 warps) ----
    if (tid < 256) {
        float ly = 0.f, lyy = 0.f, lx = 0.f, lxx = 0.f;
        for (int i = tid; i < CHK; i += 256) {
            float yv = smy[i];      ly += yv; lyy += yv * yv;
            float xv = smx[MS + i]; lx += xv; lxx += xv * xv;
        }
        #pragma unroll
        for (int o = 16; o; o >>= 1) {
            ly  += __shfl_down_sync(0xffffffffu, ly,  o);
            lyy += __shfl_down_sync(0xffffffffu, lyy, o);
            lx  += __shfl_down_sync(0xffffffffu, lx,  o);
            lxx += __shfl_down_sync(0xffffffffu, lxx, o);
        }
        if ((tid & 31) == 0) {
            int w = tid >> 5;
            wstats[w][0] = ly; wstats[w][1] = lyy;
            wstats[w][2] = lx; wstats[w][3] = lxx;
        }
    }

    // ---- shifted dot products: 8 shifts/thread, 12-float sliding window ----
    const int g  = tid % G;          // shift group: shifts [8g, 8g+8)
    const int tz = tid / G;          // time slice
    const int t0 = tz * (CHK / Z);   // multiple of 64
    const int t1 = t0 + (CHK / Z);

    const float4* x4 = reinterpret_cast<const float4*>(smx);
    const float4* y4 = reinterpret_cast<const float4*>(smy);

    float acc[8];
    #pragma unroll
    for (int j = 0; j < 8; j++) acc[j] = 0.f;

    int xi = (t0 >> 2) + 2 * g;
    float4 w0 = x4[xi];
    float4 w1 = x4[xi + 1];

    #pragma unroll 4
    for (int t = t0; t < t1; t += 4) {
        float4 w2 = x4[xi + 2];
        float4 yv = y4[t >> 2];
        float X[12] = {w0.x, w0.y, w0.z, w0.w,
                       w1.x, w1.y, w1.z, w1.w,
                       w2.x, w2.y, w2.z, w2.w};
        #pragma unroll
        for (int j = 0; j < 8; j++) {
            acc[j] += yv.x * X[j] + yv.y * X[j + 1] + yv.z * X[j + 2] + yv.w * X[j + 3];
        }
        w0 = w1;
        w1 = w2;
        xi++;
    }

    #pragma unroll
    for (int j = 0; j < 8; j++) red[tz][g][j] = acc[j];
    __syncthreads();

    // 264 threads: one (g, j) each, sum over Z slices
    if (tid < G * 8) {
        const int gg = tid >> 3;
        const int j  = tid & 7;
        float s = 0.f;
        #pragma unroll
        for (int z = 0; z < Z; z++) s += red[z][gg][j];
        g_part[pair][chunk][tid] = s;
    }
    if (tid >= 264 && tid < 268) {
        int j = tid - 264;
        float s = 0.f;
        #pragma unroll
        for (int w = 0; w < 8; w++) s += wstats[w][j];
        g_stats[pair][chunk][j] = s;
    }
    __syncthreads();

    // ---- completion handshake: last block of this pair finalizes ----
    if (tid == 0) {
        __threadfence();
        int old = atomicAdd(&g_cnt[pair], 1);
        isLast = (old == NCHUNK - 1) ? 1 : 0;
    }
    __syncthreads();
    if (!isLast) return;
    __threadfence();

    // =================== FINALIZE (one block per pair) ===================
    if (tid < MS) {
        float v = xp[tid];
        scH[tid] = make_float2(v, v * v);
    } else if (tid < 2 * MS) {
        int j = tid - MS;
        float v = xp[T - 1 - j];
        scT[j] = make_float2(v, v * v);
    } else if (tid < 2 * MS + 32) {
        // one warp gathers per-chunk stats
        int lane = tid - 2 * MS;
        float4 v = *reinterpret_cast<const float4*>(g_stats[pair][lane]);
        #pragma unroll
        for (int o = 16; o; o >>= 1) {
            v.x += __shfl_down_sync(0xffffffffu, v.x, o);
            v.y += __shfl_down_sync(0xffffffffu, v.y, o);
            v.z += __shfl_down_sync(0xffffffffu, v.z, o);
            v.w += __shfl_down_sync(0xffffffffu, v.w, o);
        }
        if (lane == 0) { tot[0] = v.x; tot[1] = v.y; tot[2] = v.z; tot[3] = v.w; }
    }
    __syncthreads();

    // Hillis-Steele inclusive scans over head and reversed tail (128 each)
    #pragma unroll
    for (int o = 1; o < MS; o <<= 1) {
        float2 v = make_float2(0.f, 0.f);
        const bool act = tid < 2 * MS;
        float2* arr = (tid < MS) ? scH : scT;
        const int j = (tid < MS) ? tid : tid - MS;
        if (act) {
            v = arr[j];
            if (j >= o) { v.x += arr[j - o].x; v.y += arr[j - o].y; }
        }
        __syncthreads();
        if (act) arr[j] = v;
        __syncthreads();
    }

    // ---- per-shift final Pearson value ----
    if (tid < S) {
        const float Sy  = tot[0], Syy = tot[1];
        const float Sx  = tot[2], Sxx = tot[3];
        const float invT = 1.0f / (float)T;
        const float my   = Sy * invT;
        const float vyy  = Syy - my * Sy;     // sum((y - my)^2)

        float part = 0.f;
        #pragma unroll
        for (int c = 0; c < NCHUNK; c++) part += g_part[pair][c][tid];

        const int d = tid - MS;
        float bx = 0.f, bxx = 0.f;
        if (d > 0)      { float2 h = scH[d - 1];   bx = h.x;  bxx = h.y; }
        else if (d < 0) { float2 t2 = scT[-d - 1]; bx = t2.x; bxx = t2.y; }

        const float wsx  = Sx  - bx;
        const float wsxx = Sxx - bxx;
        const float num  = part - my * wsx;           // sum(xw * yc)
        const float vxx  = wsxx - wsx * wsx * invT;   // sum((xw - mean_xw)^2)
        out[tid * P + pair] = num * rsqrtf(vxx * vyy);
    }

    __syncthreads();
    if (tid == 0) g_cnt[pair] = 0;   // reset for next graph replay
}

extern "C" void kernel_launch(void* const* d_in, const int* in_sizes, int n_in,
                              void* d_out, int out_size) {
    const float* x = (const float*)d_in[0];
    const float* y = (const float*)d_in[1];
    float* out = (float*)d_out;

    corr_fused<<<dim3(NCHUNK, P), BD>>>(x, y, out);
}